// round 1
// baseline (speedup 1.0000x reference)
#include <cuda_runtime.h>
#include <math.h>

// Problem constants
#define B_   4
#define V_   6
#define C_   256
#define HW_  4096
#define NH_  8
#define DH_  32
#define CHW_ (C_ * HW_)   // 1048576

// Scratch (device globals: no allocations allowed)
__device__ float g_xmean[B_ * CHW_];        // 16.8 MB  mean_v x
__device__ float g_qloc [B_ * CHW_];        // 16.8 MB  Wq * xmean
__device__ float g_kbuf [B_ * V_ * CHW_];   // 100.7 MB K projection
__device__ float g_vbuf [B_ * V_ * CHW_];   // 100.7 MB V projection
__device__ float g_att  [B_ * CHW_];        // 16.8 MB  attention output (pre out-proj)

// ---------------------------------------------------------------------------
// Kernel 1: xmean[b,c,p] = (1/6) * sum_v x[b,v,c,p]      (float4 vectorized)
// ---------------------------------------------------------------------------
__global__ void __launch_bounds__(256) xmean_kernel(const float4* __restrict__ x,
                                                    float4* __restrict__ out)
{
    const int i = blockIdx.x * blockDim.x + threadIdx.x;   // over B_*CHW_/4
    const int per_b = CHW_ / 4;
    const int b = i / per_b;
    const int r = i - b * per_b;
    const float4* src = x + (size_t)b * V_ * per_b + r;
    float sx = 0.f, sy = 0.f, sz = 0.f, sw = 0.f;
#pragma unroll
    for (int v = 0; v < V_; ++v) {
        float4 t = src[(size_t)v * per_b];
        sx += t.x; sy += t.y; sz += t.z; sw += t.w;
    }
    const float inv = 1.0f / 6.0f;
    out[i] = make_float4(sx * inv, sy * inv, sz * inv, sw * inv);
}

// ---------------------------------------------------------------------------
// Tiled SGEMM: Y[z][o][p] = sum_c W[o][c] * X[z][c][p]
//   per batch z (stride CHW_), 64x64 output tile, BK=16, 4x4 per thread.
//   NW=2 computes two weight matrices against the same X tile (K and V proj).
// ---------------------------------------------------------------------------
template <int NW>
__global__ void __launch_bounds__(256) gemm_proj(
    const float* __restrict__ W0, const float* __restrict__ W1,
    const float* __restrict__ X,
    float* __restrict__ Y0, float* __restrict__ Y1)
{
    __shared__ __align__(16) float sA[NW][16][64];  // W tile transposed: [k][o]
    __shared__ __align__(16) float sB[16][64];      // X tile: [k][p]

    const int tid = threadIdx.x;
    const int tx = tid & 15;       // p-tile position
    const int ty = tid >> 4;       // o-tile position
    const int p0 = blockIdx.x * 64;
    const int o0 = blockIdx.y * 64;
    const size_t base = (size_t)blockIdx.z * CHW_;

    // load mappings
    const int wo = tid >> 2;            // 0..63 : o row within W tile
    const int wc = (tid & 3) * 4;       // 0,4,8,12 : k offset within W tile
    const int xr = tid >> 4;            // 0..15 : k row within X tile
    const int xc = (tid & 15) * 4;      // 0..60 : p offset within X tile

    float acc0[4][4];
    float acc1[4][4];
#pragma unroll
    for (int i = 0; i < 4; ++i)
#pragma unroll
        for (int j = 0; j < 4; ++j) { acc0[i][j] = 0.f; acc1[i][j] = 0.f; }

    for (int k0 = 0; k0 < C_; k0 += 16) {
        float4 a0 = *(const float4*)(W0 + (size_t)(o0 + wo) * C_ + k0 + wc);
        float4 a1 = make_float4(0.f, 0.f, 0.f, 0.f);
        if (NW == 2) a1 = *(const float4*)(W1 + (size_t)(o0 + wo) * C_ + k0 + wc);
        float4 bx = *(const float4*)(X + base + (size_t)(k0 + xr) * HW_ + p0 + xc);

        __syncthreads();  // previous tile fully consumed
        sA[0][wc + 0][wo] = a0.x;
        sA[0][wc + 1][wo] = a0.y;
        sA[0][wc + 2][wo] = a0.z;
        sA[0][wc + 3][wo] = a0.w;
        if (NW == 2) {
            sA[1][wc + 0][wo] = a1.x;
            sA[1][wc + 1][wo] = a1.y;
            sA[1][wc + 2][wo] = a1.z;
            sA[1][wc + 3][wo] = a1.w;
        }
        *(float4*)&sB[xr][xc] = bx;
        __syncthreads();

#pragma unroll
        for (int kk = 0; kk < 16; ++kk) {
            float4 av0 = *(const float4*)&sA[0][kk][ty * 4];
            float4 bv  = *(const float4*)&sB[kk][tx * 4];
            float a[4] = {av0.x, av0.y, av0.z, av0.w};
            float bb[4] = {bv.x, bv.y, bv.z, bv.w};
#pragma unroll
            for (int i = 0; i < 4; ++i)
#pragma unroll
                for (int j = 0; j < 4; ++j)
                    acc0[i][j] += a[i] * bb[j];
            if (NW == 2) {
                float4 av1 = *(const float4*)&sA[1][kk][ty * 4];
                float a1r[4] = {av1.x, av1.y, av1.z, av1.w};
#pragma unroll
                for (int i = 0; i < 4; ++i)
#pragma unroll
                    for (int j = 0; j < 4; ++j)
                        acc1[i][j] += a1r[i] * bb[j];
            }
        }
    }

#pragma unroll
    for (int i = 0; i < 4; ++i) {
        const size_t row = base + (size_t)(o0 + ty * 4 + i) * HW_ + p0 + tx * 4;
        *(float4*)(Y0 + row) = make_float4(acc0[i][0], acc0[i][1], acc0[i][2], acc0[i][3]);
        if (NW == 2)
            *(float4*)(Y1 + row) = make_float4(acc1[i][0], acc1[i][1], acc1[i][2], acc1[i][3]);
    }
}

// ---------------------------------------------------------------------------
// Kernel: per-pixel cross-view attention.
// One thread per (b, h, p). V=6 views, dh=32. Q is the pre-averaged Qloc.
// ---------------------------------------------------------------------------
__global__ void __launch_bounds__(256) attn_kernel(
    const float* __restrict__ Q, const float* __restrict__ K,
    const float* __restrict__ Vv, float* __restrict__ O)
{
    const int p  = ((blockIdx.x & 15) << 8) + threadIdx.x;  // HW_/256 = 16 tiles
    const int bh = blockIdx.x >> 4;
    const int b  = bh >> 3;
    const int h  = bh & 7;

    const size_t qbase = ((size_t)(b * C_ + h * DH_)) * HW_ + p;

    float q[DH_];
#pragma unroll
    for (int d = 0; d < DH_; ++d) q[d] = Q[qbase + (size_t)d * HW_];

    float s[V_];
#pragma unroll
    for (int v = 0; v < V_; ++v) {
        const size_t kb = ((size_t)((b * V_ + v) * C_ + h * DH_)) * HW_ + p;
        float dot = 0.f;
#pragma unroll
        for (int d = 0; d < DH_; ++d) dot += q[d] * K[kb + (size_t)d * HW_];
        s[v] = dot * 0.17677669529663687f;   // 1/sqrt(32)
    }

    float m = s[0];
#pragma unroll
    for (int v = 1; v < V_; ++v) m = fmaxf(m, s[v]);
    float sum = 0.f;
#pragma unroll
    for (int v = 0; v < V_; ++v) { s[v] = expf(s[v] - m); sum += s[v]; }
    const float invsum = 1.f / sum;

    float acc[DH_];
#pragma unroll
    for (int d = 0; d < DH_; ++d) acc[d] = 0.f;
#pragma unroll
    for (int v = 0; v < V_; ++v) {
        const float w = s[v] * invsum;
        const size_t vb = ((size_t)((b * V_ + v) * C_ + h * DH_)) * HW_ + p;
#pragma unroll
        for (int d = 0; d < DH_; ++d) acc[d] += w * Vv[vb + (size_t)d * HW_];
    }
#pragma unroll
    for (int d = 0; d < DH_; ++d) O[qbase + (size_t)d * HW_] = acc[d];
}

// ---------------------------------------------------------------------------
// kernel_launch
// ---------------------------------------------------------------------------
extern "C" void kernel_launch(void* const* d_in, const int* in_sizes, int n_in,
                              void* d_out, int out_size)
{
    const float* x  = (const float*)d_in[0];
    const float* Wq = (const float*)d_in[1];
    const float* Wk = (const float*)d_in[2];
    const float* Wv = (const float*)d_in[3];
    const float* Wo = (const float*)d_in[4];
    float* out = (float*)d_out;

    void *pxm, *pql, *pk, *pv, *pat;
    cudaGetSymbolAddress(&pxm, g_xmean);
    cudaGetSymbolAddress(&pql, g_qloc);
    cudaGetSymbolAddress(&pk,  g_kbuf);
    cudaGetSymbolAddress(&pv,  g_vbuf);
    cudaGetSymbolAddress(&pat, g_att);
    float* xmean = (float*)pxm;
    float* qloc  = (float*)pql;
    float* kbuf  = (float*)pk;
    float* vbuf  = (float*)pv;
    float* att   = (float*)pat;

    // 1) view-mean of x
    xmean_kernel<<<(B_ * CHW_ / 4) / 256, 256>>>((const float4*)x, (float4*)xmean);

    // 2) Qloc = Wq * xmean   (per-b batch)
    {
        dim3 g(HW_ / 64, C_ / 64, B_);
        gemm_proj<1><<<g, 256>>>(Wq, nullptr, xmean, qloc, nullptr);
    }

    // 3) K,V projections (per (b,v) batch), shared x tile loads
    {
        dim3 g(HW_ / 64, C_ / 64, B_ * V_);
        gemm_proj<2><<<g, 256>>>(Wk, Wv, x, kbuf, vbuf);
    }

    // 4) per-pixel cross-view attention
    attn_kernel<<<B_ * NH_ * (HW_ / 256), 256>>>(qloc, kbuf, vbuf, att);

    // 5) out = Wo * att
    {
        dim3 g(HW_ / 64, C_ / 64, B_);
        gemm_proj<1><<<g, 256>>>(Wo, nullptr, att, out, nullptr);
    }
}

// round 3
// speedup vs baseline: 1.7010x; 1.7010x over previous
#include <cuda_runtime.h>
#include <cuda_bf16.h>
#include <cstdint>
#include <math.h>

// ---------------------------------------------------------------------------
// Problem constants
// ---------------------------------------------------------------------------
#define B_   4
#define V_   6
#define C_   256
#define HW_  4096
#define NH_  8
#define DH_  32
#define CHW_ (C_ * HW_)   // 1048576

// GEMM tiling
#define MT   128          // o tile
#define NTT  128          // p tile
#define KB   32           // k chunk
#define NKCH (C_ / KB)    // 8 chunks

// Packed smem tiles: [k2][col] b32, k2 = 16 rows, col = 128, pad to 136
#define TPAD  136
#define T_U   (16 * TPAD)               // 2176 u32 per tile
#define SMEM_MMA (2 * 4 * T_U * 4)      // 2 bufs x (AHI,ALO,BHI,BLO) = 69632 B

// ---------------------------------------------------------------------------
// Scratch (device globals: no allocations allowed)
// ---------------------------------------------------------------------------
__device__ __align__(128) float g_xmean[B_ * CHW_];
__device__ __align__(128) float g_qloc [B_ * CHW_];
__device__ __align__(128) float g_kbuf [B_ * V_ * CHW_];
__device__ __align__(128) float g_vbuf [B_ * V_ * CHW_];
__device__ __align__(128) float g_att  [B_ * CHW_];

// ---------------------------------------------------------------------------
// Helpers
// ---------------------------------------------------------------------------
__device__ __forceinline__ uint32_t packbf(float e0, float e1) {
    // low 16 bits = e0 (even k), high 16 = e1 (odd k)
    return ((uint32_t)__bfloat16_as_ushort(__float2bfloat16_rn(e1)) << 16)
         | (uint32_t)__bfloat16_as_ushort(__float2bfloat16_rn(e0));
}
__device__ __forceinline__ float bfres(float v) {
    return v - __bfloat162float(__float2bfloat16_rn(v));
}
__device__ __forceinline__ void mma16816(float* c, const uint32_t* a,
                                         uint32_t b0, uint32_t b1) {
    asm volatile(
        "mma.sync.aligned.m16n8k16.row.col.f32.bf16.bf16.f32 "
        "{%0,%1,%2,%3}, {%4,%5,%6,%7}, {%8,%9}, {%0,%1,%2,%3};\n"
        : "+f"(c[0]), "+f"(c[1]), "+f"(c[2]), "+f"(c[3])
        : "r"(a[0]), "r"(a[1]), "r"(a[2]), "r"(a[3]), "r"(b0), "r"(b1));
}

// ---------------------------------------------------------------------------
// xmean[b][c][p] = (1/6) sum_v x[b][v][c][p]
// ---------------------------------------------------------------------------
__global__ void __launch_bounds__(256) xmean_kernel(const float4* __restrict__ x,
                                                    float4* __restrict__ out)
{
    const int i = blockIdx.x * blockDim.x + threadIdx.x;
    const int per_b = CHW_ / 4;
    const int b = i / per_b;
    const int r = i - b * per_b;
    const float4* src = x + (size_t)b * V_ * per_b + r;
    float sx = 0.f, sy = 0.f, sz = 0.f, sw = 0.f;
#pragma unroll
    for (int v = 0; v < V_; ++v) {
        float4 t = src[(size_t)v * per_b];
        sx += t.x; sy += t.y; sz += t.z; sw += t.w;
    }
    const float inv = 1.0f / 6.0f;
    out[i] = make_float4(sx * inv, sy * inv, sz * inv, sw * inv);
}

// ---------------------------------------------------------------------------
// HMMA GEMM:  Y[z][o][p] = sum_c W[o][c] * X[z][c][p]
//   fp32 inputs converted in-kernel to bf16 hi/lo, 3-product split, fp32 acc.
//   KV=1: z in [0,48), view = z>>1, weight/output selected by z&1.
//   KV=0: z = batch index; single weight/output.
// grid (HW/128, C/128, nz), 256 threads, dynamic smem SMEM_MMA.
// ---------------------------------------------------------------------------
template <int KV>
__global__ void __launch_bounds__(256) gemm_mma(
    const float* __restrict__ W0, const float* __restrict__ W1,
    const float* __restrict__ X0, float* __restrict__ Y0g, float* __restrict__ Y1g)
{
    extern __shared__ __align__(16) uint32_t smem[];

    const float* W;
    const float* X;
    float* Y;
    if (KV) {
        const int view = blockIdx.z >> 1;
        const int sel = blockIdx.z & 1;
        W = sel ? W1 : W0;
        X = X0 + (size_t)view * CHW_;
        Y = (sel ? Y1g : Y0g) + (size_t)view * CHW_;
    } else {
        W = W0;
        X = X0 + (size_t)blockIdx.z * CHW_;
        Y = Y0g + (size_t)blockIdx.z * CHW_;
    }

    const int tid = threadIdx.x;
    const int lane = tid & 31;
    const int wid = tid >> 5;
    const int p0 = blockIdx.x * NTT;
    const int o0 = blockIdx.y * MT;

    // writer indices
    const int a_m  = tid >> 3;          // 0..31 (+ r*32)
    const int a_k4 = (tid & 7) * 4;     // c offset within chunk
    const int a_k2 = (tid & 7) * 2;     // packed pair row
    const int b_cp = tid >> 5;          // k-pair row 0..7 (+ r*8)
    const int b_p4 = (tid & 31) * 4;    // p offset

    // reader indices
    const int g = lane >> 2;
    const int t = lane & 3;
    const int mwb = (wid & 3) * 32;     // warp m base (warp tile 32 x 64)
    const int nwb = (wid >> 2) * 64;    // warp n base

    float acc[2][8][4];
#pragma unroll
    for (int mi = 0; mi < 2; ++mi)
#pragma unroll
        for (int ni = 0; ni < 8; ++ni)
#pragma unroll
            for (int j = 0; j < 4; ++j) acc[mi][ni][j] = 0.f;

    float4 wv[4];
    float4 xv[2][2];

    // ---- gmem load of chunk kc into registers ----
    auto load_gmem = [&](int kc) {
#pragma unroll
        for (int r = 0; r < 4; ++r)
            wv[r] = *(const float4*)(W + (size_t)(o0 + a_m + r * 32) * C_ + kc * KB + a_k4);
#pragma unroll
        for (int r = 0; r < 2; ++r) {
            const float* xb = X + (size_t)(kc * KB + (b_cp + r * 8) * 2) * HW_ + p0 + b_p4;
            xv[r][0] = *(const float4*)xb;
            xv[r][1] = *(const float4*)(xb + HW_);
        }
    };

    // ---- store registers into packed smem buffer ----
    auto store_smem = [&](int buf) {
        uint32_t* sAh = smem + (buf * 4 + 0) * T_U;
        uint32_t* sAl = smem + (buf * 4 + 1) * T_U;
        uint32_t* sBh = smem + (buf * 4 + 2) * T_U;
        uint32_t* sBl = smem + (buf * 4 + 3) * T_U;
#pragma unroll
        for (int r = 0; r < 4; ++r) {
            const int m = a_m + r * 32;
            const float4 w = wv[r];
            sAh[(a_k2 + 0) * TPAD + m] = packbf(w.x, w.y);
            sAh[(a_k2 + 1) * TPAD + m] = packbf(w.z, w.w);
            sAl[(a_k2 + 0) * TPAD + m] = packbf(bfres(w.x), bfres(w.y));
            sAl[(a_k2 + 1) * TPAD + m] = packbf(bfres(w.z), bfres(w.w));
        }
#pragma unroll
        for (int r = 0; r < 2; ++r) {
            const int cp = b_cp + r * 8;
            const float4 e = xv[r][0];   // k even row
            const float4 o = xv[r][1];   // k odd row
            uint4 h = make_uint4(packbf(e.x, o.x), packbf(e.y, o.y),
                                 packbf(e.z, o.z), packbf(e.w, o.w));
            uint4 l = make_uint4(packbf(bfres(e.x), bfres(o.x)),
                                 packbf(bfres(e.y), bfres(o.y)),
                                 packbf(bfres(e.z), bfres(o.z)),
                                 packbf(bfres(e.w), bfres(o.w)));
            *(uint4*)&sBh[cp * TPAD + b_p4] = h;
            *(uint4*)&sBl[cp * TPAD + b_p4] = l;
        }
    };

    // ---- main loop ----
    load_gmem(0);
    store_smem(0);
    __syncthreads();

    for (int kc = 0; kc < NKCH; ++kc) {
        if (kc + 1 < NKCH) load_gmem(kc + 1);

        const int buf = kc & 1;
        const uint32_t* sAh = smem + (buf * 4 + 0) * T_U;
        const uint32_t* sAl = smem + (buf * 4 + 1) * T_U;
        const uint32_t* sBh = smem + (buf * 4 + 2) * T_U;
        const uint32_t* sBl = smem + (buf * 4 + 3) * T_U;

#pragma unroll
        for (int s = 0; s < 2; ++s) {          // two k16 steps per chunk
            const int k2r0 = s * 8 + t;
            const int k2r1 = s * 8 + t + 4;
            uint32_t ah[2][4], al[2][4];
#pragma unroll
            for (int mi = 0; mi < 2; ++mi) {
                const int m0 = mwb + mi * 16 + g;
                ah[mi][0] = sAh[k2r0 * TPAD + m0];
                ah[mi][1] = sAh[k2r0 * TPAD + m0 + 8];
                ah[mi][2] = sAh[k2r1 * TPAD + m0];
                ah[mi][3] = sAh[k2r1 * TPAD + m0 + 8];
                al[mi][0] = sAl[k2r0 * TPAD + m0];
                al[mi][1] = sAl[k2r0 * TPAD + m0 + 8];
                al[mi][2] = sAl[k2r1 * TPAD + m0];
                al[mi][3] = sAl[k2r1 * TPAD + m0 + 8];
            }
#pragma unroll
            for (int ni = 0; ni < 8; ++ni) {
                const int n0 = nwb + ni * 8 + g;
                const uint32_t bh0 = sBh[k2r0 * TPAD + n0];
                const uint32_t bh1 = sBh[k2r1 * TPAD + n0];
                const uint32_t bl0 = sBl[k2r0 * TPAD + n0];
                const uint32_t bl1 = sBl[k2r1 * TPAD + n0];
#pragma unroll
                for (int mi = 0; mi < 2; ++mi) {
                    mma16816(acc[mi][ni], ah[mi], bh0, bh1);
                    mma16816(acc[mi][ni], ah[mi], bl0, bl1);
                    mma16816(acc[mi][ni], al[mi], bh0, bh1);
                }
            }
        }

        if (kc + 1 < NKCH) store_smem((kc + 1) & 1);
        __syncthreads();
    }

    // ---- epilogue: write fp32 output ----
#pragma unroll
    for (int mi = 0; mi < 2; ++mi) {
        const int o = o0 + mwb + mi * 16 + g;
#pragma unroll
        for (int ni = 0; ni < 8; ++ni) {
            const int p = p0 + nwb + ni * 8 + t * 2;
            *(float2*)(Y + (size_t)o * HW_ + p) =
                make_float2(acc[mi][ni][0], acc[mi][ni][1]);
            *(float2*)(Y + (size_t)(o + 8) * HW_ + p) =
                make_float2(acc[mi][ni][2], acc[mi][ni][3]);
        }
    }
}

// ---------------------------------------------------------------------------
// Per-pixel cross-view attention (unchanged; ~61% DRAM SOL)
// ---------------------------------------------------------------------------
__global__ void __launch_bounds__(256) attn_kernel(
    const float* __restrict__ Q, const float* __restrict__ K,
    const float* __restrict__ Vv, float* __restrict__ O)
{
    const int p = ((blockIdx.x & 15) << 8) + threadIdx.x;
    const int bh = blockIdx.x >> 4;
    const int b = bh >> 3;
    const int h = bh & 7;

    const size_t qbase = ((size_t)(b * C_ + h * DH_)) * HW_ + p;

    float q[DH_];
#pragma unroll
    for (int d = 0; d < DH_; ++d) q[d] = Q[qbase + (size_t)d * HW_];

    float s[V_];
#pragma unroll
    for (int v = 0; v < V_; ++v) {
        const size_t kb = ((size_t)((b * V_ + v) * C_ + h * DH_)) * HW_ + p;
        float dot = 0.f;
#pragma unroll
        for (int d = 0; d < DH_; ++d) dot += q[d] * K[kb + (size_t)d * HW_];
        s[v] = dot * 0.17677669529663687f;
    }
    float m = s[0];
#pragma unroll
    for (int v = 1; v < V_; ++v) m = fmaxf(m, s[v]);
    float sum = 0.f;
#pragma unroll
    for (int v = 0; v < V_; ++v) { s[v] = expf(s[v] - m); sum += s[v]; }
    const float invsum = 1.f / sum;

    float acc[DH_];
#pragma unroll
    for (int d = 0; d < DH_; ++d) acc[d] = 0.f;
#pragma unroll
    for (int v = 0; v < V_; ++v) {
        const float w = s[v] * invsum;
        const size_t vb = ((size_t)((b * V_ + v) * C_ + h * DH_)) * HW_ + p;
#pragma unroll
        for (int d = 0; d < DH_; ++d) acc[d] += w * Vv[vb + (size_t)d * HW_];
    }
#pragma unroll
    for (int d = 0; d < DH_; ++d) O[qbase + (size_t)d * HW_] = acc[d];
}

// ---------------------------------------------------------------------------
// kernel_launch
// ---------------------------------------------------------------------------
extern "C" void kernel_launch(void* const* d_in, const int* in_sizes, int n_in,
                              void* d_out, int out_size)
{
    const float* x  = (const float*)d_in[0];
    const float* Wq = (const float*)d_in[1];
    const float* Wk = (const float*)d_in[2];
    const float* Wv = (const float*)d_in[3];
    const float* Wo = (const float*)d_in[4];
    float* out = (float*)d_out;

    void* p;
    cudaGetSymbolAddress(&p, g_xmean); float* xmean = (float*)p;
    cudaGetSymbolAddress(&p, g_qloc);  float* qloc  = (float*)p;
    cudaGetSymbolAddress(&p, g_kbuf);  float* kbuf  = (float*)p;
    cudaGetSymbolAddress(&p, g_vbuf);  float* vbuf  = (float*)p;
    cudaGetSymbolAddress(&p, g_att);   float* att   = (float*)p;

    cudaFuncSetAttribute(gemm_mma<0>, cudaFuncAttributeMaxDynamicSharedMemorySize, SMEM_MMA);
    cudaFuncSetAttribute(gemm_mma<1>, cudaFuncAttributeMaxDynamicSharedMemorySize, SMEM_MMA);

    // 1) view-mean of x
    xmean_kernel<<<(B_ * CHW_ / 4) / 256, 256>>>((const float4*)x, (float4*)xmean);

    // 2) Qloc = Wq * xmean
    {
        dim3 g(HW_ / NTT, C_ / MT, B_);
        gemm_mma<0><<<g, 256, SMEM_MMA>>>(Wq, nullptr, xmean, qloc, nullptr);
    }

    // 3) K and V projections, interleaved in z for L2 reuse of x tiles
    {
        dim3 g(HW_ / NTT, C_ / MT, B_ * V_ * 2);
        gemm_mma<1><<<g, 256, SMEM_MMA>>>(Wk, Wv, x, kbuf, vbuf);
    }

    // 4) per-pixel cross-view attention
    attn_kernel<<<B_ * NH_ * (HW_ / 256), 256>>>(qloc, kbuf, vbuf, att);

    // 5) out = Wo * att
    {
        dim3 g(HW_ / NTT, C_ / MT, B_);
        gemm_mma<0><<<g, 256, SMEM_MMA>>>(Wo, nullptr, att, out, nullptr);
    }
}

// round 4
// speedup vs baseline: 2.2003x; 1.2936x over previous
#include <cuda_runtime.h>
#include <cuda_bf16.h>
#include <cstdint>
#include <math.h>

// ---------------------------------------------------------------------------
// Problem constants
// ---------------------------------------------------------------------------
#define B_   4
#define V_   6
#define C_   256
#define C2_  128          // C/2 packed pairs
#define HW_  4096
#define NH_  8
#define DH_  32
#define CHW_ (C_ * HW_)

// GEMM tiling
#define MT   128          // o tile
#define NTT  128          // p tile
#define KB   32           // k chunk (16 pairs)
#define NKCH (C_ / KB)    // 8

// smem tiles (u32 units)
#define AP    20                          // A row stride: 16 k2 + pad4
#define A_U   (MT * AP)                   // 2560
#define BPAD  136
#define B_U   (16 * BPAD)                 // 2176
#define BUF_U (2 * A_U + 2 * B_U)         // 9472  (Ah, Al, Bh, Bl)
#define SMEM_MMA (2 * BUF_U * 4)          // 75776 B

// ---------------------------------------------------------------------------
// Scratch (device globals: no allocations allowed)
// ---------------------------------------------------------------------------
__device__ __align__(128) uint32_t g_xpk_hi [B_ * V_ * C2_ * HW_];  // [(b v)][c2][p]
__device__ __align__(128) uint32_t g_xpk_lo [B_ * V_ * C2_ * HW_];
__device__ __align__(128) uint32_t g_xmpk_hi[B_ * C2_ * HW_];       // mean over v
__device__ __align__(128) uint32_t g_xmpk_lo[B_ * C2_ * HW_];
__device__ __align__(128) uint32_t g_wpk_hi [4 * C_ * C2_];         // [w][o][c2] q,k,v,o
__device__ __align__(128) uint32_t g_wpk_lo [4 * C_ * C2_];
__device__ __align__(128) uint32_t g_apk_hi [B_ * C2_ * HW_];       // attn out packed
__device__ __align__(128) uint32_t g_apk_lo [B_ * C2_ * HW_];
__device__ __align__(128) float g_qloc[B_ * CHW_];
__device__ __align__(128) float g_kbuf[B_ * V_ * CHW_];
__device__ __align__(128) float g_vbuf[B_ * V_ * CHW_];

// ---------------------------------------------------------------------------
// Helpers
// ---------------------------------------------------------------------------
__device__ __forceinline__ uint32_t smem_u32(const void* p) {
    uint32_t a;
    asm("{ .reg .u64 t; cvta.to.shared.u64 t, %1; cvt.u32.u64 %0, t; }" : "=r"(a) : "l"(p));
    return a;
}
__device__ __forceinline__ uint32_t packbf(float e0, float e1) {
    // low 16 = e0 (even k), high 16 = e1 (odd k)
    return ((uint32_t)__bfloat16_as_ushort(__float2bfloat16_rn(e1)) << 16)
         | (uint32_t)__bfloat16_as_ushort(__float2bfloat16_rn(e0));
}
__device__ __forceinline__ float bfres(float v) {
    return v - __bfloat162float(__float2bfloat16_rn(v));
}
__device__ __forceinline__ void mma16816(float* c, const uint32_t* a,
                                         uint32_t b0, uint32_t b1) {
    asm volatile(
        "mma.sync.aligned.m16n8k16.row.col.f32.bf16.bf16.f32 "
        "{%0,%1,%2,%3}, {%4,%5,%6,%7}, {%8,%9}, {%0,%1,%2,%3};\n"
        : "+f"(c[0]), "+f"(c[1]), "+f"(c[2]), "+f"(c[3])
        : "r"(a[0]), "r"(a[1]), "r"(a[2]), "r"(a[3]), "r"(b0), "r"(b1));
}
__device__ __forceinline__ void cpasync16(uint32_t dst, const void* src) {
    asm volatile("cp.async.cg.shared.global [%0], [%1], 16;\n"
                 :: "r"(dst), "l"(src));
}
#define CP_COMMIT() asm volatile("cp.async.commit_group;\n" ::: "memory")
#define CP_WAIT(n)  asm volatile("cp.async.wait_group %0;\n" :: "n"(n) : "memory")

// ---------------------------------------------------------------------------
// prep_w: split + pair-pack the four 256x256 weights. [w][o][c2]
// ---------------------------------------------------------------------------
__global__ void __launch_bounds__(256) prep_w_kernel(
    const float* __restrict__ Wq, const float* __restrict__ Wk,
    const float* __restrict__ Wv, const float* __restrict__ Wo,
    uint32_t* __restrict__ hi, uint32_t* __restrict__ lo)
{
    const int i = blockIdx.x * 256 + threadIdx.x;   // 0 .. 4*32768
    const int w = i >> 15;
    const int r = i & 32767;                        // o*128 + c2
    const float* src = (w == 0) ? Wq : (w == 1) ? Wk : (w == 2) ? Wv : Wo;
    const float2 f = *(const float2*)(src + r * 2);
    hi[i] = packbf(f.x, f.y);
    lo[i] = packbf(bfres(f.x), bfres(f.y));
}

// ---------------------------------------------------------------------------
// prep_x: fused view-mean + split + pair-pack.
//   x[b][v][c][p] fp32  ->  xpk[(b v)][c2][p] u32,  xmpk[b][c2][p] u32
// grid (HW/1024, C2, B), block 256; thread handles 4 p's.
// ---------------------------------------------------------------------------
__global__ void __launch_bounds__(256) prep_x_kernel(
    const float* __restrict__ x,
    uint32_t* __restrict__ xhi, uint32_t* __restrict__ xlo,
    uint32_t* __restrict__ mhi, uint32_t* __restrict__ mlo)
{
    const int p  = blockIdx.x * 1024 + threadIdx.x * 4;
    const int c2 = blockIdx.y;
    const int b  = blockIdx.z;

    float4 se = make_float4(0.f, 0.f, 0.f, 0.f);
    float4 so = make_float4(0.f, 0.f, 0.f, 0.f);
#pragma unroll
    for (int v = 0; v < V_; ++v) {
        const float* base = x + ((size_t)((b * V_ + v) * C_) + c2 * 2) * HW_ + p;
        const float4 e = *(const float4*)base;
        const float4 o = *(const float4*)(base + HW_);
        se.x += e.x; se.y += e.y; se.z += e.z; se.w += e.w;
        so.x += o.x; so.y += o.y; so.z += o.z; so.w += o.w;
        const size_t dst = ((size_t)(b * V_ + v) * C2_ + c2) * HW_ + p;
        *(uint4*)(xhi + dst) = make_uint4(packbf(e.x, o.x), packbf(e.y, o.y),
                                          packbf(e.z, o.z), packbf(e.w, o.w));
        *(uint4*)(xlo + dst) = make_uint4(
            packbf(bfres(e.x), bfres(o.x)), packbf(bfres(e.y), bfres(o.y)),
            packbf(bfres(e.z), bfres(o.z)), packbf(bfres(e.w), bfres(o.w)));
    }
    const float inv = 1.0f / 6.0f;
    se.x *= inv; se.y *= inv; se.z *= inv; se.w *= inv;
    so.x *= inv; so.y *= inv; so.z *= inv; so.w *= inv;
    const size_t dst = ((size_t)b * C2_ + c2) * HW_ + p;
    *(uint4*)(mhi + dst) = make_uint4(packbf(se.x, so.x), packbf(se.y, so.y),
                                      packbf(se.z, so.z), packbf(se.w, so.w));
    *(uint4*)(mlo + dst) = make_uint4(
        packbf(bfres(se.x), bfres(so.x)), packbf(bfres(se.y), bfres(so.y)),
        packbf(bfres(se.z), bfres(so.z)), packbf(bfres(se.w), bfres(so.w)));
}

// ---------------------------------------------------------------------------
// HMMA GEMM on pre-packed operands:  Y[z][o][p] = sum_c W[o][c] * X[z][c][p]
//   3-product bf16 split, fp32 accum. cp.async double-buffered.
//   KV=1: z in [0,48): view = z>>1, weight/output = z&1.
// ---------------------------------------------------------------------------
template <int KV>
__global__ void __launch_bounds__(256) gemm_pk(
    const uint32_t* __restrict__ Wh0, const uint32_t* __restrict__ Wl0,
    const uint32_t* __restrict__ Wh1, const uint32_t* __restrict__ Wl1,
    const uint32_t* __restrict__ Xh,  const uint32_t* __restrict__ Xl,
    float* __restrict__ Y0g, float* __restrict__ Y1g)
{
    extern __shared__ __align__(16) uint32_t smem[];
    const uint32_t sb = smem_u32(smem);

    const uint32_t *Wh, *Wl, *Xhz, *Xlz;
    float* Y;
    if (KV) {
        const int view = blockIdx.z >> 1;
        const int sel = blockIdx.z & 1;
        Wh = sel ? Wh1 : Wh0;
        Wl = sel ? Wl1 : Wl0;
        const size_t xoff = (size_t)view * C2_ * HW_;
        Xhz = Xh + xoff; Xlz = Xl + xoff;
        Y = (sel ? Y1g : Y0g) + (size_t)view * CHW_;
    } else {
        Wh = Wh0; Wl = Wl0;
        const size_t xoff = (size_t)blockIdx.z * C2_ * HW_;
        Xhz = Xh + xoff; Xlz = Xl + xoff;
        Y = Y0g + (size_t)blockIdx.z * CHW_;
    }

    const int tid = threadIdx.x;
    const int lane = tid & 31;
    const int wid = tid >> 5;
    const int p0 = blockIdx.x * NTT;
    const int o0 = blockIdx.y * MT;

    // async-copy indices
    const int a_o  = tid >> 2;          // 0..63 (+64 second pass)
    const int a_k4 = (tid & 3) * 4;     // pair offset
    const int b_r  = tid >> 5;          // 0..7 (+8 second pass)
    const int b_p4 = (tid & 31) * 4;

    // mma fragment indices
    const int g = lane >> 2;
    const int t = lane & 3;
    const int mwb = (wid & 3) * 32;
    const int nwb = (wid >> 2) * 64;

    float acc[2][8][4];
#pragma unroll
    for (int mi = 0; mi < 2; ++mi)
#pragma unroll
        for (int ni = 0; ni < 8; ++ni)
#pragma unroll
            for (int j = 0; j < 4; ++j) acc[mi][ni][j] = 0.f;

    auto issue = [&](int kc, int buf) {
        const uint32_t base = sb + buf * BUF_U * 4;
        const uint32_t dAh = base;
        const uint32_t dAl = base + A_U * 4;
        const uint32_t dBh = base + 2 * A_U * 4;
        const uint32_t dBl = base + (2 * A_U + B_U) * 4;
#pragma unroll
        for (int r = 0; r < 2; ++r) {
            const int o = a_o + r * 64;
            const size_t wsrc = (size_t)(o0 + o) * C2_ + kc * 16 + a_k4;
            const uint32_t wdst = (o * AP + a_k4) * 4;
            cpasync16(dAh + wdst, Wh + wsrc);
            cpasync16(dAl + wdst, Wl + wsrc);
            const int row = b_r + r * 8;
            const size_t xsrc = (size_t)(kc * 16 + row) * HW_ + p0 + b_p4;
            const uint32_t xdst = (row * BPAD + b_p4) * 4;
            cpasync16(dBh + xdst, Xhz + xsrc);
            cpasync16(dBl + xdst, Xlz + xsrc);
        }
        CP_COMMIT();
    };

    issue(0, 0);

    for (int kc = 0; kc < NKCH; ++kc) {
        if (kc + 1 < NKCH) {
            issue(kc + 1, (kc + 1) & 1);
            CP_WAIT(1);
        } else {
            CP_WAIT(0);
        }
        __syncthreads();

        const uint32_t* bb = smem + (kc & 1) * BUF_U;
        const uint32_t* sAh = bb;
        const uint32_t* sAl = bb + A_U;
        const uint32_t* sBh = bb + 2 * A_U;
        const uint32_t* sBl = bb + 2 * A_U + B_U;

#pragma unroll
        for (int s = 0; s < 2; ++s) {
            const int k2r0 = s * 8 + t;
            const int k2r1 = s * 8 + t + 4;
            uint32_t ah[2][4], al[2][4];
#pragma unroll
            for (int mi = 0; mi < 2; ++mi) {
                const int m0 = mwb + mi * 16 + g;
                ah[mi][0] = sAh[m0 * AP + k2r0];
                ah[mi][1] = sAh[(m0 + 8) * AP + k2r0];
                ah[mi][2] = sAh[m0 * AP + k2r1];
                ah[mi][3] = sAh[(m0 + 8) * AP + k2r1];
                al[mi][0] = sAl[m0 * AP + k2r0];
                al[mi][1] = sAl[(m0 + 8) * AP + k2r0];
                al[mi][2] = sAl[m0 * AP + k2r1];
                al[mi][3] = sAl[(m0 + 8) * AP + k2r1];
            }
#pragma unroll
            for (int ni = 0; ni < 8; ++ni) {
                const int n0 = nwb + ni * 8 + g;
                const uint32_t bh0 = sBh[k2r0 * BPAD + n0];
                const uint32_t bh1 = sBh[k2r1 * BPAD + n0];
                const uint32_t bl0 = sBl[k2r0 * BPAD + n0];
                const uint32_t bl1 = sBl[k2r1 * BPAD + n0];
#pragma unroll
                for (int mi = 0; mi < 2; ++mi) {
                    mma16816(acc[mi][ni], ah[mi], bh0, bh1);
                    mma16816(acc[mi][ni], ah[mi], bl0, bl1);
                    mma16816(acc[mi][ni], al[mi], bh0, bh1);
                }
            }
        }
        __syncthreads();
    }

    // epilogue
#pragma unroll
    for (int mi = 0; mi < 2; ++mi) {
        const int o = o0 + mwb + mi * 16 + g;
#pragma unroll
        for (int ni = 0; ni < 8; ++ni) {
            const int p = p0 + nwb + ni * 8 + t * 2;
            *(float2*)(Y + (size_t)o * HW_ + p) =
                make_float2(acc[mi][ni][0], acc[mi][ni][1]);
            *(float2*)(Y + (size_t)(o + 8) * HW_ + p) =
                make_float2(acc[mi][ni][2], acc[mi][ni][3]);
        }
    }
}

// ---------------------------------------------------------------------------
// Per-pixel cross-view attention; emits pair-packed bf16 hi/lo output.
// ---------------------------------------------------------------------------
__global__ void __launch_bounds__(256) attn_kernel(
    const float* __restrict__ Q, const float* __restrict__ K,
    const float* __restrict__ Vv,
    uint32_t* __restrict__ Ohi, uint32_t* __restrict__ Olo)
{
    const int p = ((blockIdx.x & 15) << 8) + threadIdx.x;
    const int bh = blockIdx.x >> 4;
    const int b = bh >> 3;
    const int h = bh & 7;

    const size_t qbase = ((size_t)(b * C_ + h * DH_)) * HW_ + p;

    float q[DH_];
#pragma unroll
    for (int d = 0; d < DH_; ++d) q[d] = Q[qbase + (size_t)d * HW_];

    float s[V_];
#pragma unroll
    for (int v = 0; v < V_; ++v) {
        const size_t kb = ((size_t)((b * V_ + v) * C_ + h * DH_)) * HW_ + p;
        float dot = 0.f;
#pragma unroll
        for (int d = 0; d < DH_; ++d) dot += q[d] * K[kb + (size_t)d * HW_];
        s[v] = dot * 0.17677669529663687f;
    }
    float m = s[0];
#pragma unroll
    for (int v = 1; v < V_; ++v) m = fmaxf(m, s[v]);
    float sum = 0.f;
#pragma unroll
    for (int v = 0; v < V_; ++v) { s[v] = expf(s[v] - m); sum += s[v]; }
    const float invsum = 1.f / sum;

    float acc[DH_];
#pragma unroll
    for (int d = 0; d < DH_; ++d) acc[d] = 0.f;
#pragma unroll
    for (int v = 0; v < V_; ++v) {
        const float w = s[v] * invsum;
        const size_t vb = ((size_t)((b * V_ + v) * C_ + h * DH_)) * HW_ + p;
#pragma unroll
        for (int d = 0; d < DH_; ++d) acc[d] += w * Vv[vb + (size_t)d * HW_];
    }
    const size_t obase = ((size_t)(b * C2_ + h * (DH_ / 2))) * HW_ + p;
#pragma unroll
    for (int d2 = 0; d2 < DH_ / 2; ++d2) {
        const float e0 = acc[d2 * 2], e1 = acc[d2 * 2 + 1];
        Ohi[obase + (size_t)d2 * HW_] = packbf(e0, e1);
        Olo[obase + (size_t)d2 * HW_] = packbf(bfres(e0), bfres(e1));
    }
}

// ---------------------------------------------------------------------------
// kernel_launch
// ---------------------------------------------------------------------------
extern "C" void kernel_launch(void* const* d_in, const int* in_sizes, int n_in,
                              void* d_out, int out_size)
{
    const float* x  = (const float*)d_in[0];
    const float* Wq = (const float*)d_in[1];
    const float* Wk = (const float*)d_in[2];
    const float* Wv = (const float*)d_in[3];
    const float* Wo = (const float*)d_in[4];
    float* out = (float*)d_out;

    void* p;
    cudaGetSymbolAddress(&p, g_xpk_hi);  uint32_t* xhi = (uint32_t*)p;
    cudaGetSymbolAddress(&p, g_xpk_lo);  uint32_t* xlo = (uint32_t*)p;
    cudaGetSymbolAddress(&p, g_xmpk_hi); uint32_t* mhi = (uint32_t*)p;
    cudaGetSymbolAddress(&p, g_xmpk_lo); uint32_t* mlo = (uint32_t*)p;
    cudaGetSymbolAddress(&p, g_wpk_hi);  uint32_t* whi = (uint32_t*)p;
    cudaGetSymbolAddress(&p, g_wpk_lo);  uint32_t* wlo = (uint32_t*)p;
    cudaGetSymbolAddress(&p, g_apk_hi);  uint32_t* ahi = (uint32_t*)p;
    cudaGetSymbolAddress(&p, g_apk_lo);  uint32_t* alo = (uint32_t*)p;
    cudaGetSymbolAddress(&p, g_qloc);    float* qloc = (float*)p;
    cudaGetSymbolAddress(&p, g_kbuf);    float* kbuf = (float*)p;
    cudaGetSymbolAddress(&p, g_vbuf);    float* vbuf = (float*)p;

    cudaFuncSetAttribute(gemm_pk<0>, cudaFuncAttributeMaxDynamicSharedMemorySize, SMEM_MMA);
    cudaFuncSetAttribute(gemm_pk<1>, cudaFuncAttributeMaxDynamicSharedMemorySize, SMEM_MMA);

    const int WSZ = C_ * C2_;   // 32768 u32 per weight

    // 1) prep: weights + x (fused mean)
    prep_w_kernel<<<4 * WSZ / 256, 256>>>(Wq, Wk, Wv, Wo, whi, wlo);
    {
        dim3 g(HW_ / 1024, C2_, B_);
        prep_x_kernel<<<g, 256>>>(x, xhi, xlo, mhi, mlo);
    }

    // 2) Qloc = Wq * xmean
    {
        dim3 g(HW_ / NTT, C_ / MT, B_);
        gemm_pk<0><<<g, 256, SMEM_MMA>>>(whi + 0 * WSZ, wlo + 0 * WSZ,
                                         nullptr, nullptr, mhi, mlo, qloc, nullptr);
    }

    // 3) K and V projections (z-interleaved for X reuse in L2)
    {
        dim3 g(HW_ / NTT, C_ / MT, B_ * V_ * 2);
        gemm_pk<1><<<g, 256, SMEM_MMA>>>(whi + 1 * WSZ, wlo + 1 * WSZ,
                                         whi + 2 * WSZ, wlo + 2 * WSZ,
                                         xhi, xlo, kbuf, vbuf);
    }

    // 4) attention (emits packed hi/lo)
    attn_kernel<<<B_ * NH_ * (HW_ / 256), 256>>>(qloc, kbuf, vbuf, ahi, alo);

    // 5) out = Wo * att
    {
        dim3 g(HW_ / NTT, C_ / MT, B_);
        gemm_pk<0><<<g, 256, SMEM_MMA>>>(whi + 3 * WSZ, wlo + 3 * WSZ,
                                         nullptr, nullptr, ahi, alo, out, nullptr);
    }
}